// round 15
// baseline (speedup 1.0000x reference)
#include <cuda_runtime.h>
#include <cuda_fp16.h>

#define EPS 1e-4f
#define NDIM 512
#define H2S 131072   // half2 per sample

typedef unsigned long long u64;

__device__ __half2 g_half[128 * (size_t)H2S];   // 64 MB fp16 working copy (zero-init)

__device__ __forceinline__ float4 z4f() { return make_float4(0.f, 0.f, 0.f, 0.f); }
__device__ __forceinline__ u64 fma2(u64 a, u64 b, u64 c) {
    u64 d; asm("fma.rn.f32x2 %0, %1, %2, %3;" : "=l"(d) : "l"(a), "l"(b), "l"(c)); return d;
}
__device__ __forceinline__ u64 mul2(u64 a, u64 b) {
    u64 d; asm("mul.rn.f32x2 %0, %1, %2;" : "=l"(d) : "l"(a), "l"(b)); return d;
}
__device__ __forceinline__ u64 add2(u64 a, u64 b) {
    u64 d; asm("add.rn.f32x2 %0, %1, %2;" : "=l"(d) : "l"(a), "l"(b)); return d;
}
__device__ __forceinline__ u64 pk2(float x, float y) {
    u64 r; asm("mov.b64 %0, {%1, %2};" : "=l"(r) : "f"(x), "f"(y)); return r;
}
__device__ __forceinline__ float2 unpk(u64 p) {
    float2 f; asm("mov.b64 {%0, %1}, %2;" : "=f"(f.x), "=f"(f.y) : "l"(p)); return f;
}
__device__ __forceinline__ u64 h2pk(unsigned u) {
    __half2 h = *reinterpret_cast<__half2*>(&u);
    float2 f = __half22float2(h);
    return pk2(f.x, f.y);
}
__device__ __forceinline__ float2 pack_h4(float4 v) {
    __half2 h0 = __floats2half2_rn(v.x, v.y);
    __half2 h1 = __floats2half2_rn(v.z, v.w);
    float2 r;
    r.x = __uint_as_float(*reinterpret_cast<unsigned*>(&h0));
    r.y = __uint_as_float(*reinterpret_cast<unsigned*>(&h1));
    return r;
}
__device__ __forceinline__ void st_cs_v2u64(void* p, u64 a, u64 b) {
    asm volatile("st.global.cs.v2.u64 [%0], {%1, %2};" :: "l"(p), "l"(a), "l"(b) : "memory");
}
// convert one fp16 row slice (16 halves) into 8 packed f32x2 pairs
__device__ __forceinline__ void cvt_row(u64* p, uint4 u0, uint4 u1) {
    p[0] = h2pk(u0.x); p[1] = h2pk(u0.y); p[2] = h2pk(u0.z); p[3] = h2pk(u0.w);
    p[4] = h2pk(u1.x); p[5] = h2pk(u1.y); p[6] = h2pk(u1.z); p[7] = h2pk(u1.w);
}
__device__ __forceinline__ float dot_pk(const u64* p,
                                        ulonglong2 cA, ulonglong2 cB,
                                        ulonglong2 cC, ulonglong2 cD) {
    u64 d0 = mul2(p[0], cA.x), d1 = mul2(p[1], cA.y);
    u64 d2 = mul2(p[2], cB.x), d3 = mul2(p[3], cB.y);
    d0 = fma2(p[4], cC.x, d0); d1 = fma2(p[5], cC.y, d1);
    d2 = fma2(p[6], cD.x, d2); d3 = fma2(p[7], cD.y, d3);
    d0 = add2(d0, d1); d2 = add2(d2, d3); d0 = add2(d0, d2);
    float2 f = unpk(d0);
    return f.x + f.y;
}

__global__ __launch_bounds__(512, 1)
void sinkhorn_kernel(const float* __restrict__ s,
                     const int* __restrict__ nrows,
                     float* __restrict__ out) {
    extern __shared__ __align__(16) float red[];        // 16*512 floats = 32 KB
    __shared__ __align__(16) float c_sh[NDIM];
    __shared__ float ssumA[16];
    __shared__ float ssumB[16];

    const int b    = blockIdx.x;
    const int tid  = threadIdx.x;
    const int lane = tid & 31;
    const int wid  = tid >> 5;                           // 0..15
    const int n    = nrows[b];
    const bool g2  = (n > 256);
    const float* __restrict__ S = s   + (size_t)b * (NDIM * NDIM);
    float* __restrict__       O = out + (size_t)b * (NDIM * NDIM);
    __half2* __restrict__     H = g_half + (size_t)b * H2S;
    const ulonglong2* __restrict__ cs64 = (const ulonglong2*)c_sh;

    // ===== pass 0: column sums (r = 1) + fp16 conversion, MLP-8 load pipeline ===
    {
        const int j4    = (tid & 127) << 2;
        const int jh    = j4 >> 1;
        const int slice = tid >> 7;                      // 0..3
        float4 a0 = z4f(), a1 = z4f(), a2 = z4f(), a3 = z4f();
        if (j4 < n) {
            int i = slice;
            for (; i + 28 < n; i += 32) {
                float4 v0 = __ldcs((const float4*)(S + (size_t)(i)      * NDIM + j4));
                float4 v1 = __ldcs((const float4*)(S + (size_t)(i + 4)  * NDIM + j4));
                float4 v2 = __ldcs((const float4*)(S + (size_t)(i + 8)  * NDIM + j4));
                float4 v3 = __ldcs((const float4*)(S + (size_t)(i + 12) * NDIM + j4));
                float4 v4 = __ldcs((const float4*)(S + (size_t)(i + 16) * NDIM + j4));
                float4 v5 = __ldcs((const float4*)(S + (size_t)(i + 20) * NDIM + j4));
                float4 v6 = __ldcs((const float4*)(S + (size_t)(i + 24) * NDIM + j4));
                float4 v7 = __ldcs((const float4*)(S + (size_t)(i + 28) * NDIM + j4));
                a0.x += v0.x + v4.x; a0.y += v0.y + v4.y;
                a0.z += v0.z + v4.z; a0.w += v0.w + v4.w;
                a1.x += v1.x + v5.x; a1.y += v1.y + v5.y;
                a1.z += v1.z + v5.z; a1.w += v1.w + v5.w;
                a2.x += v2.x + v6.x; a2.y += v2.y + v6.y;
                a2.z += v2.z + v6.z; a2.w += v2.w + v6.w;
                a3.x += v3.x + v7.x; a3.y += v3.y + v7.y;
                a3.z += v3.z + v7.z; a3.w += v3.w + v7.w;
                *(float2*)(H + (size_t)(i)      * (NDIM/2) + jh) = pack_h4(v0);
                *(float2*)(H + (size_t)(i + 4)  * (NDIM/2) + jh) = pack_h4(v1);
                *(float2*)(H + (size_t)(i + 8)  * (NDIM/2) + jh) = pack_h4(v2);
                *(float2*)(H + (size_t)(i + 12) * (NDIM/2) + jh) = pack_h4(v3);
                *(float2*)(H + (size_t)(i + 16) * (NDIM/2) + jh) = pack_h4(v4);
                *(float2*)(H + (size_t)(i + 20) * (NDIM/2) + jh) = pack_h4(v5);
                *(float2*)(H + (size_t)(i + 24) * (NDIM/2) + jh) = pack_h4(v6);
                *(float2*)(H + (size_t)(i + 28) * (NDIM/2) + jh) = pack_h4(v7);
            }
            for (; i < n; i += 4) {
                float4 v0 = __ldcs((const float4*)(S + (size_t)i * NDIM + j4));
                a0.x += v0.x; a0.y += v0.y; a0.z += v0.z; a0.w += v0.w;
                *(float2*)(H + (size_t)i * (NDIM/2) + jh) = pack_h4(v0);
            }
            a0.x += a1.x + a2.x + a3.x; a0.y += a1.y + a2.y + a3.y;
            a0.z += a1.z + a2.z + a3.z; a0.w += a1.w + a2.w + a3.w;
        }
        *(float4*)(red + slice * NDIM + j4) = a0;
        __syncthreads();

        float cv = 0.0f;
        {
            float cs = red[tid] + red[NDIM + tid] + red[2 * NDIM + tid] + red[3 * NDIM + tid];
            if (tid < n) cv = 1.0f / (cs + EPS * (float)n);
            c_sh[tid] = cv;
        }
        float v = cv;
        #pragma unroll
        for (int o = 16; o; o >>= 1) v += __shfl_xor_sync(0xffffffffu, v, o);
        if (lane == 0) ssumB[wid] = v;
        __syncthreads();
    }
    float sum_c = 0.0f;
    #pragma unroll
    for (int k = 0; k < 16; ++k) sum_c += ssumB[k];

    // === 4 fused passes: row+col; 2-row batch, convert-once, f32x2 math ========
    #pragma unroll 1
    for (int f = 0; f < 4; ++f) {
        const float eps_c = EPS * sum_c;
        u64 acc[8];
        #pragma unroll
        for (int k = 0; k < 8; ++k) acc[k] = 0ull;
        float rpart = 0.0f;
        const uint4 uz = make_uint4(0u, 0u, 0u, 0u);

        int i = wid;
        uint4 uA0 = uz, uA1 = uz, uB0 = uz, uB1 = uz;
        if (i < n) {
            const uint4* __restrict__ rA = (const uint4*)(H + (size_t)i * (NDIM/2));
            uA0 = rA[lane];
            if (g2) uA1 = rA[lane + 32];
        }
        if (i + 16 < n) {
            const uint4* __restrict__ rB = (const uint4*)(H + (size_t)(i + 16) * (NDIM/2));
            uB0 = rB[lane];
            if (g2) uB1 = rB[lane + 32];
        }
        #pragma unroll 1
        while (i < n) {
            const int inx = i + 32;
            uint4 nA0 = uz, nA1 = uz, nB0 = uz, nB1 = uz;
            if (inx < n) {
                const uint4* __restrict__ rN = (const uint4*)(H + (size_t)inx * (NDIM/2));
                nA0 = rN[lane];
                if (g2) nA1 = rN[lane + 32];
            }
            if (inx + 16 < n) {
                const uint4* __restrict__ rN = (const uint4*)(H + (size_t)(inx + 16) * (NDIM/2));
                nB0 = rN[lane];
                if (g2) nB1 = rN[lane + 32];
            }

            // convert ONCE per row; reuse packed values for dot and acc
            u64 pA[8], pB[8];
            cvt_row(pA, uA0, uA1);
            cvt_row(pB, uB0, uB1);
            const ulonglong2 cA = cs64[2 * lane],      cB = cs64[2 * lane + 1];
            const ulonglong2 cC = cs64[64 + 2 * lane], cD = cs64[64 + 2 * lane + 1];

            float tA = dot_pk(pA, cA, cB, cC, cD);
            float tB = dot_pk(pB, cA, cB, cC, cD);
            #pragma unroll
            for (int o = 16; o; o >>= 1) {
                tA += __shfl_xor_sync(0xffffffffu, tA, o);
                tB += __shfl_xor_sync(0xffffffffu, tB, o);
            }
            const float riA = 1.0f / (tA + eps_c);
            const float riB = 1.0f / (tB + eps_c);
            const u64 rpkA = pk2(riA, riA);
            rpart += riA;
            #pragma unroll
            for (int k = 0; k < 8; ++k) acc[k] = fma2(rpkA, pA[k], acc[k]);
            if (i + 16 < n) {
                const u64 rpkB = pk2(riB, riB);
                rpart += riB;
                #pragma unroll
                for (int k = 0; k < 8; ++k) acc[k] = fma2(rpkB, pB[k], acc[k]);
            }
            uA0 = nA0; uA1 = nA1; uB0 = nB0; uB1 = nB1; i = inx;
        }

        ulonglong2* __restrict__ rw = (ulonglong2*)(red + wid * NDIM);
        rw[2 * lane]          = make_ulonglong2(acc[0], acc[1]);
        rw[2 * lane + 1]      = make_ulonglong2(acc[2], acc[3]);
        rw[64 + 2 * lane]     = make_ulonglong2(acc[4], acc[5]);
        rw[64 + 2 * lane + 1] = make_ulonglong2(acc[6], acc[7]);
        if (lane == 0) ssumA[wid] = rpart;   // warp-uniform
        __syncthreads();

        float sum_r = 0.0f;
        #pragma unroll
        for (int k = 0; k < 16; ++k) sum_r += ssumA[k];

        float cv = 0.0f;
        {
            float cs = 0.0f;
            #pragma unroll
            for (int w = 0; w < 16; ++w) cs += red[w * NDIM + tid];
            if (tid < n) cv = 1.0f / (cs + EPS * sum_r);
            c_sh[tid] = cv;
        }
        float v = cv;
        #pragma unroll
        for (int o = 16; o; o >>= 1) v += __shfl_xor_sync(0xffffffffu, v, o);
        if (lane == 0) ssumB[wid] = v;
        __syncthreads();
        sum_c = 0.0f;
        #pragma unroll
        for (int k = 0; k < 16; ++k) sum_c += ssumB[k];
    }

    // === final pass: row step (iter 9), convert-once + f32x2 epilogue ==========
    {
        const float eps_c = EPS * sum_c;
        const uint4 uz = make_uint4(0u, 0u, 0u, 0u);
        const u64 epk = pk2(EPS, EPS);

        for (int i = wid; i < n; i += 32) {
            const int i2 = i + 16;
            const uint4* __restrict__ rA = (const uint4*)(H + (size_t)i * (NDIM/2));
            uint4 uA0 = __ldcs(rA + lane);
            uint4 uA1 = uz;
            if (g2) uA1 = __ldcs(rA + lane + 32);
            uint4 uB0 = uz, uB1 = uz;
            if (i2 < n) {
                const uint4* __restrict__ rB = (const uint4*)(H + (size_t)i2 * (NDIM/2));
                uB0 = __ldcs(rB + lane);
                if (g2) uB1 = __ldcs(rB + lane + 32);
            }

            u64 pA[8], pB[8];
            cvt_row(pA, uA0, uA1);
            cvt_row(pB, uB0, uB1);
            const ulonglong2 cA = cs64[2 * lane],      cB = cs64[2 * lane + 1];
            const ulonglong2 cC = cs64[64 + 2 * lane], cD = cs64[64 + 2 * lane + 1];

            float tA = dot_pk(pA, cA, cB, cC, cD);
            float tB = dot_pk(pB, cA, cB, cC, cD);
            #pragma unroll
            for (int o = 16; o; o >>= 1) {
                tA += __shfl_xor_sync(0xffffffffu, tA, o);
                tB += __shfl_xor_sync(0xffffffffu, tB, o);
            }
            const float riA = 1.0f / (tA + eps_c);
            const float riB = 1.0f / (tB + eps_c);

            {
                const u64 rpk = pk2(riA, riA);
                float4* __restrict__ orow = (float4*)(O + (size_t)i * NDIM);
                u64 w0 = mul2(mul2(add2(pA[0], epk), rpk), cA.x);
                u64 w1 = mul2(mul2(add2(pA[1], epk), rpk), cA.y);
                st_cs_v2u64(orow + 2 * lane, w0, w1);
                w0 = mul2(mul2(add2(pA[2], epk), rpk), cB.x);
                w1 = mul2(mul2(add2(pA[3], epk), rpk), cB.y);
                st_cs_v2u64(orow + 2 * lane + 1, w0, w1);
                w0 = mul2(mul2(add2(pA[4], epk), rpk), cC.x);
                w1 = mul2(mul2(add2(pA[5], epk), rpk), cC.y);
                st_cs_v2u64(orow + 64 + 2 * lane, w0, w1);
                w0 = mul2(mul2(add2(pA[6], epk), rpk), cD.x);
                w1 = mul2(mul2(add2(pA[7], epk), rpk), cD.y);
                st_cs_v2u64(orow + 64 + 2 * lane + 1, w0, w1);
            }
            if (i2 < n) {
                const u64 rpk = pk2(riB, riB);
                float4* __restrict__ orow = (float4*)(O + (size_t)i2 * NDIM);
                u64 w0 = mul2(mul2(add2(pB[0], epk), rpk), cA.x);
                u64 w1 = mul2(mul2(add2(pB[1], epk), rpk), cA.y);
                st_cs_v2u64(orow + 2 * lane, w0, w1);
                w0 = mul2(mul2(add2(pB[2], epk), rpk), cB.x);
                w1 = mul2(mul2(add2(pB[3], epk), rpk), cB.y);
                st_cs_v2u64(orow + 2 * lane + 1, w0, w1);
                w0 = mul2(mul2(add2(pB[4], epk), rpk), cC.x);
                w1 = mul2(mul2(add2(pB[5], epk), rpk), cC.y);
                st_cs_v2u64(orow + 64 + 2 * lane, w0, w1);
                w0 = mul2(mul2(add2(pB[6], epk), rpk), cD.x);
                w1 = mul2(mul2(add2(pB[7], epk), rpk), cD.y);
                st_cs_v2u64(orow + 64 + 2 * lane + 1, w0, w1);
            }
        }
        // zero-fill rows i >= n
        float4* __restrict__ O4 = (float4*)O;
        const float4 z = z4f();
        for (int idx = n * 128 + tid; idx < NDIM * 128; idx += 512)
            __stcs(O4 + idx, z);
    }
}

extern "C" void kernel_launch(void* const* d_in, const int* in_sizes, int n_in,
                              void* d_out, int out_size) {
    const float* s     = (const float*)d_in[0];
    const int*   nrows = (const int*)d_in[1];
    float*       out   = (float*)d_out;
    const int B = in_sizes[1];
    const int shbytes = 16 * NDIM * sizeof(float);   // 32 KB dynamic
    static bool attr_set = false;
    if (!attr_set) {
        cudaFuncSetAttribute(sinkhorn_kernel,
                             cudaFuncAttributeMaxDynamicSharedMemorySize, shbytes);
        attr_set = true;
    }
    sinkhorn_kernel<<<B, 512, shbytes>>>(s, nrows, out);
}

// round 16
// speedup vs baseline: 1.0870x; 1.0870x over previous
#include <cuda_runtime.h>
#include <cuda_fp16.h>

#define EPS 1e-4f
#define NDIM 512
#define H2S 131072   // half2 per sample

__device__ __half2 g_half[128 * (size_t)H2S];   // 64 MB fp16 working copy (zero-init)

__device__ __forceinline__ float4 z4f() { return make_float4(0.f, 0.f, 0.f, 0.f); }
__device__ __forceinline__ float2 h2f(unsigned u) {
    __half2 h = *reinterpret_cast<__half2*>(&u);
    return __half22float2(h);
}
__device__ __forceinline__ float2 pack_h4(float4 v) {
    __half2 h0 = __floats2half2_rn(v.x, v.y);
    __half2 h1 = __floats2half2_rn(v.z, v.w);
    float2 r;
    r.x = __uint_as_float(*reinterpret_cast<unsigned*>(&h0));
    r.y = __uint_as_float(*reinterpret_cast<unsigned*>(&h1));
    return r;
}
// dot of one fp16 row (u0: cols 8L..8L+7, u1: cols 256+8L..+7) with c in regs
__device__ __forceinline__ float dot_row(uint4 u0, uint4 u1,
                                         float4 c0, float4 c1,
                                         float4 c2, float4 c3) {
    float2 f0 = h2f(u0.x), f1 = h2f(u0.y), f2 = h2f(u0.z), f3 = h2f(u0.w);
    float2 f4 = h2f(u1.x), f5 = h2f(u1.y), f6 = h2f(u1.z), f7 = h2f(u1.w);
    float d0 = 0.f, d1 = 0.f, d2 = 0.f, d3 = 0.f;
    d0 = fmaf(f0.x, c0.x, d0); d1 = fmaf(f0.y, c0.y, d1);
    d2 = fmaf(f1.x, c0.z, d2); d3 = fmaf(f1.y, c0.w, d3);
    d0 = fmaf(f2.x, c1.x, d0); d1 = fmaf(f2.y, c1.y, d1);
    d2 = fmaf(f3.x, c1.z, d2); d3 = fmaf(f3.y, c1.w, d3);
    d0 = fmaf(f4.x, c2.x, d0); d1 = fmaf(f4.y, c2.y, d1);
    d2 = fmaf(f5.x, c2.z, d2); d3 = fmaf(f5.y, c2.w, d3);
    d0 = fmaf(f6.x, c3.x, d0); d1 = fmaf(f6.y, c3.y, d1);
    d2 = fmaf(f7.x, c3.z, d2); d3 = fmaf(f7.y, c3.w, d3);
    return (d0 + d1) + (d2 + d3);
}
__device__ __forceinline__ void acc_row(float4& a0, float4& a1, float4& a2, float4& a3,
                                        uint4 u0, uint4 u1, float ri) {
    float2 f0 = h2f(u0.x), f1 = h2f(u0.y), f2 = h2f(u0.z), f3 = h2f(u0.w);
    a0.x = fmaf(ri, f0.x, a0.x); a0.y = fmaf(ri, f0.y, a0.y);
    a0.z = fmaf(ri, f1.x, a0.z); a0.w = fmaf(ri, f1.y, a0.w);
    a1.x = fmaf(ri, f2.x, a1.x); a1.y = fmaf(ri, f2.y, a1.y);
    a1.z = fmaf(ri, f3.x, a1.z); a1.w = fmaf(ri, f3.y, a1.w);
    float2 f4 = h2f(u1.x), f5 = h2f(u1.y), f6 = h2f(u1.z), f7 = h2f(u1.w);
    a2.x = fmaf(ri, f4.x, a2.x); a2.y = fmaf(ri, f4.y, a2.y);
    a2.z = fmaf(ri, f5.x, a2.z); a2.w = fmaf(ri, f5.y, a2.w);
    a3.x = fmaf(ri, f6.x, a3.x); a3.y = fmaf(ri, f6.y, a3.y);
    a3.z = fmaf(ri, f7.x, a3.z); a3.w = fmaf(ri, f7.y, a3.w);
}

__global__ __launch_bounds__(512, 1)
void sinkhorn_kernel(const float* __restrict__ s,
                     const int* __restrict__ nrows,
                     float* __restrict__ out) {
    extern __shared__ __align__(16) float red[];        // 16*512 floats = 32 KB
    __shared__ __align__(16) float c_sh[NDIM];
    __shared__ float ssumA[16];
    __shared__ float ssumB[16];

    const int b    = blockIdx.x;
    const int tid  = threadIdx.x;
    const int lane = tid & 31;
    const int wid  = tid >> 5;                           // 0..15
    const int n    = nrows[b];
    const bool g2  = (n > 256);
    const float* __restrict__ S = s   + (size_t)b * (NDIM * NDIM);
    float* __restrict__       O = out + (size_t)b * (NDIM * NDIM);
    __half2* __restrict__     H = g_half + (size_t)b * H2S;
    const float4* __restrict__ c4s = (const float4*)c_sh;

    // ===== pass 0: column sums (r = 1) + fp16 conversion, MLP-8 load pipeline ===
    {
        const int j4    = (tid & 127) << 2;
        const int jh    = j4 >> 1;
        const int slice = tid >> 7;                      // 0..3
        float4 a0 = z4f(), a1 = z4f(), a2 = z4f(), a3 = z4f();
        if (j4 < n) {
            int i = slice;
            for (; i + 28 < n; i += 32) {
                float4 v0 = __ldcs((const float4*)(S + (size_t)(i)      * NDIM + j4));
                float4 v1 = __ldcs((const float4*)(S + (size_t)(i + 4)  * NDIM + j4));
                float4 v2 = __ldcs((const float4*)(S + (size_t)(i + 8)  * NDIM + j4));
                float4 v3 = __ldcs((const float4*)(S + (size_t)(i + 12) * NDIM + j4));
                float4 v4 = __ldcs((const float4*)(S + (size_t)(i + 16) * NDIM + j4));
                float4 v5 = __ldcs((const float4*)(S + (size_t)(i + 20) * NDIM + j4));
                float4 v6 = __ldcs((const float4*)(S + (size_t)(i + 24) * NDIM + j4));
                float4 v7 = __ldcs((const float4*)(S + (size_t)(i + 28) * NDIM + j4));
                a0.x += v0.x + v4.x; a0.y += v0.y + v4.y;
                a0.z += v0.z + v4.z; a0.w += v0.w + v4.w;
                a1.x += v1.x + v5.x; a1.y += v1.y + v5.y;
                a1.z += v1.z + v5.z; a1.w += v1.w + v5.w;
                a2.x += v2.x + v6.x; a2.y += v2.y + v6.y;
                a2.z += v2.z + v6.z; a2.w += v2.w + v6.w;
                a3.x += v3.x + v7.x; a3.y += v3.y + v7.y;
                a3.z += v3.z + v7.z; a3.w += v3.w + v7.w;
                *(float2*)(H + (size_t)(i)      * (NDIM/2) + jh) = pack_h4(v0);
                *(float2*)(H + (size_t)(i + 4)  * (NDIM/2) + jh) = pack_h4(v1);
                *(float2*)(H + (size_t)(i + 8)  * (NDIM/2) + jh) = pack_h4(v2);
                *(float2*)(H + (size_t)(i + 12) * (NDIM/2) + jh) = pack_h4(v3);
                *(float2*)(H + (size_t)(i + 16) * (NDIM/2) + jh) = pack_h4(v4);
                *(float2*)(H + (size_t)(i + 20) * (NDIM/2) + jh) = pack_h4(v5);
                *(float2*)(H + (size_t)(i + 24) * (NDIM/2) + jh) = pack_h4(v6);
                *(float2*)(H + (size_t)(i + 28) * (NDIM/2) + jh) = pack_h4(v7);
            }
            for (; i < n; i += 4) {
                float4 v0 = __ldcs((const float4*)(S + (size_t)i * NDIM + j4));
                a0.x += v0.x; a0.y += v0.y; a0.z += v0.z; a0.w += v0.w;
                *(float2*)(H + (size_t)i * (NDIM/2) + jh) = pack_h4(v0);
            }
            a0.x += a1.x + a2.x + a3.x; a0.y += a1.y + a2.y + a3.y;
            a0.z += a1.z + a2.z + a3.z; a0.w += a1.w + a2.w + a3.w;
        }
        *(float4*)(red + slice * NDIM + j4) = a0;
        __syncthreads();

        float cv = 0.0f;
        {
            float cs = red[tid] + red[NDIM + tid] + red[2 * NDIM + tid] + red[3 * NDIM + tid];
            if (tid < n) cv = __fdividef(1.0f, cs + EPS * (float)n);
            c_sh[tid] = cv;                              // 512 threads = 512 cols
        }
        float v = cv;
        #pragma unroll
        for (int o = 16; o; o >>= 1) v += __shfl_xor_sync(0xffffffffu, v, o);
        if (lane == 0) ssumB[wid] = v;
        __syncthreads();
    }
    float sum_c = 0.0f;
    #pragma unroll
    for (int k = 0; k < 16; ++k) sum_c += ssumB[k];

    // === 4 fused passes: row(2f+1)+col(2f+2); 2-row batch + 2-row lookahead =====
    #pragma unroll 1
    for (int f = 0; f < 4; ++f) {
        const float eps_c = EPS * sum_c;
        float4 acc0 = z4f(), acc1 = z4f(), acc2 = z4f(), acc3 = z4f();
        float rpart = 0.0f;
        const uint4 uz = make_uint4(0u, 0u, 0u, 0u);

        const float4 c0 = c4s[lane * 2],      c1 = c4s[lane * 2 + 1];
        const float4 c2 = c4s[64 + lane * 2], c3 = c4s[64 + lane * 2 + 1];

        int i = wid;
        uint4 uA0 = uz, uA1 = uz, uB0 = uz, uB1 = uz;
        if (i < n) {
            const uint4* __restrict__ rA = (const uint4*)(H + (size_t)i * (NDIM/2));
            uA0 = rA[lane];
            if (g2) uA1 = rA[lane + 32];
        }
        if (i + 16 < n) {
            const uint4* __restrict__ rB = (const uint4*)(H + (size_t)(i + 16) * (NDIM/2));
            uB0 = rB[lane];
            if (g2) uB1 = rB[lane + 32];
        }
        #pragma unroll 1
        while (i < n) {
            const int inx = i + 32;
            uint4 nA0 = uz, nA1 = uz, nB0 = uz, nB1 = uz;
            if (inx < n) {
                const uint4* __restrict__ rN = (const uint4*)(H + (size_t)inx * (NDIM/2));
                nA0 = rN[lane];
                if (g2) nA1 = rN[lane + 32];
            }
            if (inx + 16 < n) {
                const uint4* __restrict__ rN = (const uint4*)(H + (size_t)(inx + 16) * (NDIM/2));
                nB0 = rN[lane];
                if (g2) nB1 = rN[lane + 32];
            }

            float tA = dot_row(uA0, uA1, c0, c1, c2, c3);
            float tB = dot_row(uB0, uB1, c0, c1, c2, c3);
            #pragma unroll
            for (int o = 16; o; o >>= 1) {
                tA += __shfl_xor_sync(0xffffffffu, tA, o);
                tB += __shfl_xor_sync(0xffffffffu, tB, o);
            }
            const float riA = __fdividef(1.0f, tA + eps_c);
            const float riB = __fdividef(1.0f, tB + eps_c);
            rpart += riA;
            acc_row(acc0, acc1, acc2, acc3, uA0, uA1, riA);
            if (i + 16 < n) {                // second row real?
                rpart += riB;
                acc_row(acc0, acc1, acc2, acc3, uB0, uB1, riB);
            }
            uA0 = nA0; uA1 = nA1; uB0 = nB0; uB1 = nB1; i = inx;
        }

        float4* __restrict__ rw = (float4*)(red + wid * NDIM);
        rw[lane * 2]          = acc0;
        rw[lane * 2 + 1]      = acc1;
        rw[64 + lane * 2]     = acc2;
        rw[64 + lane * 2 + 1] = acc3;
        if (lane == 0) ssumA[wid] = rpart;   // warp-uniform
        __syncthreads();

        float sum_r = 0.0f;
        #pragma unroll
        for (int k = 0; k < 16; ++k) sum_r += ssumA[k];

        float cv = 0.0f;
        {
            float cs = 0.0f;
            #pragma unroll
            for (int w = 0; w < 16; ++w) cs += red[w * NDIM + tid];
            if (tid < n) cv = __fdividef(1.0f, cs + EPS * sum_r);
            c_sh[tid] = cv;
        }
        float v = cv;
        #pragma unroll
        for (int o = 16; o; o >>= 1) v += __shfl_xor_sync(0xffffffffu, v, o);
        if (lane == 0) ssumB[wid] = v;
        __syncthreads();
        sum_c = 0.0f;
        #pragma unroll
        for (int k = 0; k < 16; ++k) sum_c += ssumB[k];
    }

    // === final pass: row step (iter 9) on fp16 copy, 2-row batch, fused write ===
    {
        const float eps_c = EPS * sum_c;
        const uint4 uz = make_uint4(0u, 0u, 0u, 0u);
        const float4 c0 = c4s[lane * 2],      c1 = c4s[lane * 2 + 1];
        const float4 c2 = c4s[64 + lane * 2], c3 = c4s[64 + lane * 2 + 1];

        for (int i = wid; i < n; i += 32) {
            const int i2 = i + 16;
            const uint4* __restrict__ rA = (const uint4*)(H + (size_t)i * (NDIM/2));
            uint4 uA0 = __ldcs(rA + lane);
            uint4 uA1 = uz;
            if (g2) uA1 = __ldcs(rA + lane + 32);
            uint4 uB0 = uz, uB1 = uz;
            if (i2 < n) {
                const uint4* __restrict__ rB = (const uint4*)(H + (size_t)i2 * (NDIM/2));
                uB0 = __ldcs(rB + lane);
                if (g2) uB1 = __ldcs(rB + lane + 32);
            }

            float tA = dot_row(uA0, uA1, c0, c1, c2, c3);
            float tB = dot_row(uB0, uB1, c0, c1, c2, c3);
            #pragma unroll
            for (int o = 16; o; o >>= 1) {
                tA += __shfl_xor_sync(0xffffffffu, tA, o);
                tB += __shfl_xor_sync(0xffffffffu, tB, o);
            }
            const float riA = __fdividef(1.0f, tA + eps_c);
            const float riB = __fdividef(1.0f, tB + eps_c);

            {
                float4* __restrict__ orow = (float4*)(O + (size_t)i * NDIM);
                float2 f0 = h2f(uA0.x), f1 = h2f(uA0.y), f2 = h2f(uA0.z), f3 = h2f(uA0.w);
                float2 f4 = h2f(uA1.x), f5 = h2f(uA1.y), f6 = h2f(uA1.z), f7 = h2f(uA1.w);
                float4 w;
                w.x = (f0.x + EPS) * riA * c0.x; w.y = (f0.y + EPS) * riA * c0.y;
                w.z = (f1.x + EPS) * riA * c0.z; w.w = (f1.y + EPS) * riA * c0.w;
                __stcs(orow + lane * 2, w);
                w.x = (f2.x + EPS) * riA * c1.x; w.y = (f2.y + EPS) * riA * c1.y;
                w.z = (f3.x + EPS) * riA * c1.z; w.w = (f3.y + EPS) * riA * c1.w;
                __stcs(orow + lane * 2 + 1, w);
                w.x = (f4.x + EPS) * riA * c2.x; w.y = (f4.y + EPS) * riA * c2.y;
                w.z = (f5.x + EPS) * riA * c2.z; w.w = (f5.y + EPS) * riA * c2.w;
                __stcs(orow + 64 + lane * 2, w);
                w.x = (f6.x + EPS) * riA * c3.x; w.y = (f6.y + EPS) * riA * c3.y;
                w.z = (f7.x + EPS) * riA * c3.z; w.w = (f7.y + EPS) * riA * c3.w;
                __stcs(orow + 64 + lane * 2 + 1, w);
            }
            if (i2 < n) {
                float4* __restrict__ orow = (float4*)(O + (size_t)i2 * NDIM);
                float2 f0 = h2f(uB0.x), f1 = h2f(uB0.y), f2 = h2f(uB0.z), f3 = h2f(uB0.w);
                float2 f4 = h2f(uB1.x), f5 = h2f(uB1.y), f6 = h2f(uB1.z), f7 = h2f(uB1.w);
                float4 w;
                w.x = (f0.x + EPS) * riB * c0.x; w.y = (f0.y + EPS) * riB * c0.y;
                w.z = (f1.x + EPS) * riB * c0.z; w.w = (f1.y + EPS) * riB * c0.w;
                __stcs(orow + lane * 2, w);
                w.x = (f2.x + EPS) * riB * c1.x; w.y = (f2.y + EPS) * riB * c1.y;
                w.z = (f3.x + EPS) * riB * c1.z; w.w = (f3.y + EPS) * riB * c1.w;
                __stcs(orow + lane * 2 + 1, w);
                w.x = (f4.x + EPS) * riB * c2.x; w.y = (f4.y + EPS) * riB * c2.y;
                w.z = (f5.x + EPS) * riB * c2.z; w.w = (f5.y + EPS) * riB * c2.w;
                __stcs(orow + 64 + lane * 2, w);
                w.x = (f6.x + EPS) * riB * c3.x; w.y = (f6.y + EPS) * riB * c3.y;
                w.z = (f7.x + EPS) * riB * c3.z; w.w = (f7.y + EPS) * riB * c3.w;
                __stcs(orow + 64 + lane * 2 + 1, w);
            }
        }
        // zero-fill rows i >= n
        float4* __restrict__ O4 = (float4*)O;
        const float4 z = z4f();
        for (int idx = n * 128 + tid; idx < NDIM * 128; idx += 512)
            __stcs(O4 + idx, z);
    }
}

extern "C" void kernel_launch(void* const* d_in, const int* in_sizes, int n_in,
                              void* d_out, int out_size) {
    const float* s     = (const float*)d_in[0];
    const int*   nrows = (const int*)d_in[1];
    float*       out   = (float*)d_out;
    const int B = in_sizes[1];
    const int shbytes = 16 * NDIM * sizeof(float);   // 32 KB dynamic
    static bool attr_set = false;
    if (!attr_set) {
        cudaFuncSetAttribute(sinkhorn_kernel,
                             cudaFuncAttributeMaxDynamicSharedMemorySize, shbytes);
        attr_set = true;
    }
    sinkhorn_kernel<<<B, 512, shbytes>>>(s, nrows, out);
}